// round 14
// baseline (speedup 1.0000x reference)
#include <cuda_runtime.h>
#include <math.h>
#include <stdint.h>

// ---------------------------------------------------------------------------
// MultilayerGRU  B=64 S=1024 I=128 H=512 L=3 O=128
// Persistent cooperative kernel, 128 CTAs x 512 threads.
// Thread (q=tid>>5, sub=lane>>4, bl=lane&15) handles b = bl+{0,16,32,48}
// (R=4 batch blocking) and a 16-k sub-slice for all 4 CTA output columns.
// Pass A: z,r over (h,x). Pass B: g over x.  Packed fp32x2 FMAs.
// shfl_xor(16) merges sub-slices -> 16-deep SMEM reduction (as R13).
// 6 grid barriers per timestep.
// ---------------------------------------------------------------------------

#define NCTA 128
#define NTHR 512
#define Bx   64
#define Sx   1024
#define Ix   128
#define Hx   512
#define Lx   3
#define Ox   128
#define CPT  4
#define HQ   (Hx/4)     // 128 float4 per activation row
#define IQ   (Ix/4)     // 32

// ---- shared memory layout (float offsets) ----
#define WHZ0 0
#define WHR0 2048
#define WHG0 4096
#define WX0Z 6144
#define WX0R 6656
#define WX0G 7168
#define WXZ1 7680
#define WXR1 9728
#define WXG1 11776
#define WHZ1 13824
#define WHR1 15872
#define WHG1 17920
#define WXZ2 19968
#define WXR2 22016
#define WXG2 24064
#define WHZ2 26112
#define WHR2 28160
#define WHG2 30208
#define WYOF 32256
#define SM_RED 32768            // 16 deep * 16 slots * 64 b = 16384 floats
#define SM_BZ  49152
#define SM_BR  49168
#define SM_BG  49184
#define SM_BY  49200
#define SMEM_FLOATS 49216
#define SMEM_BYTES  (SMEM_FLOATS * 4)

// ---- global scratch ----
__device__ float4 g_x0t[(size_t)Sx * IQ * Bx];   // [s][j4][b]
__device__ float4 g_h[Lx * HQ * Bx];             // [l][k4][b]
__device__ float4 g_rh[HQ * Bx];                 // [k4][b]
__device__ unsigned g_bar;

// ---------------------------------------------------------------------------
__device__ __forceinline__ unsigned long long pfma(unsigned long long a,
                                                   unsigned long long b,
                                                   unsigned long long c) {
    unsigned long long d;
    asm("fma.rn.f32x2 %0, %1, %2, %3;" : "=l"(d) : "l"(a), "l"(b), "l"(c));
    return d;
}

__device__ __forceinline__ float phsum(unsigned long long v) {
    float lo = __uint_as_float((unsigned)(v & 0xffffffffULL));
    float hi = __uint_as_float((unsigned)(v >> 32));
    return lo + hi;
}

__device__ __forceinline__ float fsigm(float x) {
    return __fdividef(1.f, 1.f + __expf(-x));
}
__device__ __forceinline__ float ftanh(float x) {
    float e = __expf(-2.f * x);
    return __fdividef(1.f - e, 1.f + e);
}

__device__ __forceinline__ void gbar(unsigned target) {
    __syncthreads();
    if (threadIdx.x == 0) {
        unsigned* p = &g_bar;
        asm volatile("red.release.gpu.global.add.u32 [%0], 1;" :: "l"(p) : "memory");
        unsigned v;
        do {
            asm volatile("ld.acquire.gpu.global.u32 %0, [%1];" : "=r"(v) : "l"(p) : "memory");
        } while (v < target);
    }
    __syncthreads();
}

// ---------------------------------------------------------------------------
// Two-gate dot over NIT float4-iterations for 4 b-values x 4 columns.
template<int NIT>
__device__ __forceinline__ void dot2(
    unsigned long long az[4][4], unsigned long long ar[4][4],
    const ulonglong2* __restrict__ src, int base, int bl,
    const ulonglong2* __restrict__ w1, const ulonglong2* __restrict__ w2,
    int wstr)
{
#pragma unroll
    for (int i = 0; i < NIT; i++) {
        const int k4 = base + i;
        ulonglong2 a0 = src[k4 * Bx + bl];
        ulonglong2 a1 = src[k4 * Bx + bl + 16];
        ulonglong2 a2 = src[k4 * Bx + bl + 32];
        ulonglong2 a3 = src[k4 * Bx + bl + 48];
#pragma unroll
        for (int cp = 0; cp < 4; cp++) {
            ulonglong2 wz = w1[cp * wstr + k4];
            ulonglong2 wr = w2[cp * wstr + k4];
            az[0][cp] = pfma(a0.x, wz.x, az[0][cp]);
            az[1][cp] = pfma(a1.x, wz.x, az[1][cp]);
            az[2][cp] = pfma(a2.x, wz.x, az[2][cp]);
            az[3][cp] = pfma(a3.x, wz.x, az[3][cp]);
            ar[0][cp] = pfma(a0.x, wr.x, ar[0][cp]);
            ar[1][cp] = pfma(a1.x, wr.x, ar[1][cp]);
            ar[2][cp] = pfma(a2.x, wr.x, ar[2][cp]);
            ar[3][cp] = pfma(a3.x, wr.x, ar[3][cp]);
            az[0][cp] = pfma(a0.y, wz.y, az[0][cp]);
            az[1][cp] = pfma(a1.y, wz.y, az[1][cp]);
            az[2][cp] = pfma(a2.y, wz.y, az[2][cp]);
            az[3][cp] = pfma(a3.y, wz.y, az[3][cp]);
            ar[0][cp] = pfma(a0.y, wr.y, ar[0][cp]);
            ar[1][cp] = pfma(a1.y, wr.y, ar[1][cp]);
            ar[2][cp] = pfma(a2.y, wr.y, ar[2][cp]);
            ar[3][cp] = pfma(a3.y, wr.y, ar[3][cp]);
        }
    }
}

// Single-gate dot.
template<int NIT>
__device__ __forceinline__ void dot1(
    unsigned long long ag[4][4],
    const ulonglong2* __restrict__ src, int base, int bl,
    const ulonglong2* __restrict__ w, int wstr)
{
#pragma unroll
    for (int i = 0; i < NIT; i++) {
        const int k4 = base + i;
        ulonglong2 a0 = src[k4 * Bx + bl];
        ulonglong2 a1 = src[k4 * Bx + bl + 16];
        ulonglong2 a2 = src[k4 * Bx + bl + 32];
        ulonglong2 a3 = src[k4 * Bx + bl + 48];
#pragma unroll
        for (int cp = 0; cp < 4; cp++) {
            ulonglong2 wg = w[cp * wstr + k4];
            ag[0][cp] = pfma(a0.x, wg.x, ag[0][cp]);
            ag[1][cp] = pfma(a1.x, wg.x, ag[1][cp]);
            ag[2][cp] = pfma(a2.x, wg.x, ag[2][cp]);
            ag[3][cp] = pfma(a3.x, wg.x, ag[3][cp]);
            ag[0][cp] = pfma(a0.y, wg.y, ag[0][cp]);
            ag[1][cp] = pfma(a1.y, wg.y, ag[1][cp]);
            ag[2][cp] = pfma(a2.y, wg.y, ag[2][cp]);
            ag[3][cp] = pfma(a3.y, wg.y, ag[3][cp]);
        }
    }
}

// Merge sub-halves via shfl_xor(16), store 16 partials (4 cp x 4 b) at slot0+cp.
__device__ __forceinline__ void mstore(
    float* sw, int q, int sub, int bl, int slot0,
    unsigned long long acc[4][4])
{
#pragma unroll
    for (int cp = 0; cp < 4; cp++)
#pragma unroll
        for (int r = 0; r < 4; r++) {
            float v = phsum(acc[r][cp]);
            v += __shfl_xor_sync(0xffffffffu, v, 16);
            if (sub == 0)
                sw[SM_RED + (q * 16 + slot0 + cp) * Bx + bl + 16 * r] = v;
        }
}

// Phase-1 finalize: warps q<4 own column c=q; lanes handle b=lane, lane+32.
__device__ __forceinline__ void p1_final(
    float* sw, int lane, int q, int cta, int l,
    const float* __restrict__ hbase,
    float2& z_reg, float2& xg_reg)
{
    if (q >= 4) return;
    const int c = q;
    float zz[2], xx[2];
#pragma unroll
    for (int r = 0; r < 2; r++) {
        const int b = lane + 32 * r;
        float sz = 0.f, sr = 0.f, sg = 0.f;
#pragma unroll
        for (int qq = 0; qq < 16; qq++) {
            sz += sw[SM_RED + (qq * 16 + c)     * Bx + b];
            sr += sw[SM_RED + (qq * 16 + 4 + c) * Bx + b];
            sg += sw[SM_RED + (qq * 16 + 8 + c) * Bx + b];
        }
        float z  = fsigm(sz + sw[SM_BZ + l * 4 + c]);
        float rr = fsigm(sr + sw[SM_BR + l * 4 + c]);
        zz[r] = z;
        xx[r] = sg + sw[SM_BG + l * 4 + c];
        float hcur = hbase[(cta * Bx + b) * 4 + c];
        ((float*)g_rh)[(cta * Bx + b) * 4 + c] = rr * hcur;
    }
    z_reg  = make_float2(zz[0], zz[1]);
    xg_reg = make_float2(xx[0], xx[1]);
}

__device__ __forceinline__ void p2_final(
    float* sw, int lane, int q, int cta, int l, float2 z_reg, float2 xg_reg)
{
    if (q >= 4) return;
    const int c = q;
#pragma unroll
    for (int r = 0; r < 2; r++) {
        const int b = lane + 32 * r;
        float s = 0.f;
#pragma unroll
        for (int qq = 0; qq < 16; qq++)
            s += sw[SM_RED + (qq * 16 + c) * Bx + b];
        float xg = (r == 0) ? xg_reg.x : xg_reg.y;
        float z  = (r == 0) ? z_reg.x  : z_reg.y;
        float g = ftanh(s + xg);
        float* hp = ((float*)g_h) + (((size_t)l * HQ + cta) * Bx + b) * 4 + c;
        float hold = *hp;
        *hp = fmaf(z, hold - g, g);
    }
}

// Output-projection partial over h2 (folded into P01 of step t+1).
__device__ __forceinline__ void y_partial(float* sw, int bl, int sub, int q)
{
    const ulonglong2* h2  = (const ulonglong2*)(g_h + 2 * HQ * Bx);
    const ulonglong2* wy2 = (const ulonglong2*)(sw + WYOF);
    unsigned long long ay[4] = {0ULL, 0ULL, 0ULL, 0ULL};
    const int base = q * 8 + sub * 4;
#pragma unroll
    for (int i = 0; i < 4; i++) {
        const int k4 = base + i;
        ulonglong2 w  = wy2[k4];
        ulonglong2 a0 = h2[k4 * Bx + bl];
        ulonglong2 a1 = h2[k4 * Bx + bl + 16];
        ulonglong2 a2 = h2[k4 * Bx + bl + 32];
        ulonglong2 a3 = h2[k4 * Bx + bl + 48];
        ay[0] = pfma(a0.x, w.x, ay[0]);
        ay[1] = pfma(a1.x, w.x, ay[1]);
        ay[2] = pfma(a2.x, w.x, ay[2]);
        ay[3] = pfma(a3.x, w.x, ay[3]);
        ay[0] = pfma(a0.y, w.y, ay[0]);
        ay[1] = pfma(a1.y, w.y, ay[1]);
        ay[2] = pfma(a2.y, w.y, ay[2]);
        ay[3] = pfma(a3.y, w.y, ay[3]);
    }
#pragma unroll
    for (int r = 0; r < 4; r++) {
        float v = phsum(ay[r]);
        v += __shfl_xor_sync(0xffffffffu, v, 16);
        if (sub == 0)
            sw[SM_RED + (q * 16 + 12) * Bx + bl + 16 * r] = v;
    }
}

__device__ __forceinline__ void y_final(float* sw, int lane, int cta,
                                        float* __restrict__ out, int tdst)
{
#pragma unroll
    for (int r = 0; r < 2; r++) {
        const int b = lane + 32 * r;
        float s = 0.f;
#pragma unroll
        for (int qq = 0; qq < 16; qq++)
            s += sw[SM_RED + (qq * 16 + 12) * Bx + b];
        out[((size_t)b * Sx + tdst) * Ox + cta] = s + sw[SM_BY];
    }
}

// ---------------------------------------------------------------------------
__global__ void init_kernel(const float* __restrict__ in, const float* __restrict__ hs)
{
    size_t i = (size_t)blockIdx.x * blockDim.x + threadIdx.x;
    size_t stride = (size_t)gridDim.x * blockDim.x;
    if (i == 0) g_bar = 0;

    for (size_t idx = i; idx < (size_t)Bx * Lx * Hx; idx += stride) {
        int b = (int)(idx / (Lx * Hx));
        int l = (int)((idx / Hx) % Lx);
        int k = (int)(idx % Hx);
        ((float*)g_h)[(((size_t)l * HQ + (k >> 2)) * Bx + b) * 4 + (k & 3)] = hs[idx];
    }
    for (size_t idx = i; idx < (size_t)Bx * Sx * Ix; idx += stride) {
        int b = (int)(idx / ((size_t)Sx * Ix));
        int s = (int)((idx / Ix) % Sx);
        int j = (int)(idx % Ix);
        ((float*)g_x0t)[(((size_t)s * IQ + (j >> 2)) * Bx + b) * 4 + (j & 3)] = in[idx];
    }
}

__global__ void __launch_bounds__(NTHR, 1) gru_main(
    const float* __restrict__ Wx0z, const float* __restrict__ Wx0r, const float* __restrict__ Wx0g,
    const float* __restrict__ Wxz,  const float* __restrict__ Wxr,  const float* __restrict__ Wxg,
    const float* __restrict__ Whz,  const float* __restrict__ Whr,  const float* __restrict__ Whg,
    const float* __restrict__ bz,   const float* __restrict__ br,   const float* __restrict__ bg,
    const float* __restrict__ Wy,   const float* __restrict__ by,
    float* __restrict__ out)
{
    extern __shared__ float sw[];
    const int tid = threadIdx.x;
    const int cta = blockIdx.x;
    const int nb  = cta * CPT;

    // ---- load this CTA's weight slices into SMEM (once) ----
    for (int i = tid; i < CPT * Hx; i += NTHR) {
        int cp = i >> 9, k = i & 511;
        int row = nb + cp;
        sw[WHZ0 + i] = Whz[((size_t)(0 * Hx + row)) * Hx + k];
        sw[WHR0 + i] = Whr[((size_t)(0 * Hx + row)) * Hx + k];
        sw[WHG0 + i] = Whg[((size_t)(0 * Hx + row)) * Hx + k];
        sw[WHZ1 + i] = Whz[((size_t)(1 * Hx + row)) * Hx + k];
        sw[WHR1 + i] = Whr[((size_t)(1 * Hx + row)) * Hx + k];
        sw[WHG1 + i] = Whg[((size_t)(1 * Hx + row)) * Hx + k];
        sw[WHZ2 + i] = Whz[((size_t)(2 * Hx + row)) * Hx + k];
        sw[WHR2 + i] = Whr[((size_t)(2 * Hx + row)) * Hx + k];
        sw[WHG2 + i] = Whg[((size_t)(2 * Hx + row)) * Hx + k];
        sw[WXZ1 + i] = Wxz[((size_t)(0 * Hx + row)) * Hx + k];
        sw[WXR1 + i] = Wxr[((size_t)(0 * Hx + row)) * Hx + k];
        sw[WXG1 + i] = Wxg[((size_t)(0 * Hx + row)) * Hx + k];
        sw[WXZ2 + i] = Wxz[((size_t)(1 * Hx + row)) * Hx + k];
        sw[WXR2 + i] = Wxr[((size_t)(1 * Hx + row)) * Hx + k];
        sw[WXG2 + i] = Wxg[((size_t)(1 * Hx + row)) * Hx + k];
    }
    for (int i = tid; i < CPT * Ix; i += NTHR) {
        int cp = i >> 7, j = i & 127;
        int row = nb + cp;
        sw[WX0Z + i] = Wx0z[(size_t)row * Ix + j];
        sw[WX0R + i] = Wx0r[(size_t)row * Ix + j];
        sw[WX0G + i] = Wx0g[(size_t)row * Ix + j];
    }
    for (int i = tid; i < Hx; i += NTHR)
        sw[WYOF + i] = Wy[(size_t)cta * Hx + i];
    if (tid < 12) {
        int l = tid >> 2, cp = tid & 3;
        sw[SM_BZ + tid] = bz[l * Hx + nb + cp];
        sw[SM_BR + tid] = br[l * Hx + nb + cp];
        sw[SM_BG + tid] = bg[l * Hx + nb + cp];
    }
    if (tid == 0) sw[SM_BY] = by[cta];
    __syncthreads();

    const int lane = tid & 31;
    const int q    = tid >> 5;       // 16 k-slices (each split again by sub)
    const int sub  = lane >> 4;      // k sub-half
    const int bl   = lane & 15;      // b base

    const ulonglong2* h0u = (const ulonglong2*)(g_h);
    const ulonglong2* h1u = (const ulonglong2*)(g_h + 1 * HQ * Bx);
    const ulonglong2* h2u = (const ulonglong2*)(g_h + 2 * HQ * Bx);
    const ulonglong2* rhu = (const ulonglong2*)g_rh;

    const ulonglong2* wz0p = (const ulonglong2*)(sw + WHZ0);
    const ulonglong2* wr0p = (const ulonglong2*)(sw + WHR0);
    const ulonglong2* wg0p = (const ulonglong2*)(sw + WHG0);
    const ulonglong2* x0zp = (const ulonglong2*)(sw + WX0Z);
    const ulonglong2* x0rp = (const ulonglong2*)(sw + WX0R);
    const ulonglong2* x0gp = (const ulonglong2*)(sw + WX0G);
    const ulonglong2* wz1p = (const ulonglong2*)(sw + WHZ1);
    const ulonglong2* wr1p = (const ulonglong2*)(sw + WHR1);
    const ulonglong2* wg1p = (const ulonglong2*)(sw + WHG1);
    const ulonglong2* x1zp = (const ulonglong2*)(sw + WXZ1);
    const ulonglong2* x1rp = (const ulonglong2*)(sw + WXR1);
    const ulonglong2* x1gp = (const ulonglong2*)(sw + WXG1);
    const ulonglong2* wz2p = (const ulonglong2*)(sw + WHZ2);
    const ulonglong2* wr2p = (const ulonglong2*)(sw + WHR2);
    const ulonglong2* wg2p = (const ulonglong2*)(sw + WHG2);
    const ulonglong2* x2zp = (const ulonglong2*)(sw + WXZ2);
    const ulonglong2* x2rp = (const ulonglong2*)(sw + WXR2);
    const ulonglong2* x2gp = (const ulonglong2*)(sw + WXG2);

    const int hb = q * 8 + sub * 4;  // h/rh float4 base (4 iters)
    const int xb = q * 2 + sub;      // layer-0 x float4 base (1 iter)

    float2 z_reg = make_float2(0.f, 0.f), xg_reg = make_float2(0.f, 0.f);
    unsigned bv = 0;

    for (int t = 0; t < Sx; t++) {
        const ulonglong2* xt = (const ulonglong2*)(g_x0t + (size_t)t * IQ * Bx);

        // ---- P(0,1): layer-0 z/r (pass A), g x-part (pass B), + y(t-1) ----
        {
            unsigned long long az[4][4], ar[4][4];
#pragma unroll
            for (int r = 0; r < 4; r++)
#pragma unroll
                for (int cp = 0; cp < 4; cp++) { az[r][cp] = 0ULL; ar[r][cp] = 0ULL; }
            dot2<4>(az, ar, h0u, hb, bl, wz0p, wr0p, 128);
            dot2<1>(az, ar, xt,  xb, bl, x0zp, x0rp, 32);
            mstore(sw, q, sub, bl, 0, az);
            mstore(sw, q, sub, bl, 4, ar);
        }
        {
            unsigned long long ag[4][4];
#pragma unroll
            for (int r = 0; r < 4; r++)
#pragma unroll
                for (int cp = 0; cp < 4; cp++) ag[r][cp] = 0ULL;
            dot1<1>(ag, xt, xb, bl, x0gp, 32);
            mstore(sw, q, sub, bl, 8, ag);
        }
        if (t > 0) y_partial(sw, bl, sub, q);
        __syncthreads();
        p1_final(sw, lane, q, cta, 0, (const float*)g_h, z_reg, xg_reg);
        if (t > 0 && q == 4) y_final(sw, lane, cta, out, t - 1);
        bv++; gbar(bv * NCTA);

        // ---- P(0,2): g-dot over rh ----
        {
            unsigned long long ag[4][4];
#pragma unroll
            for (int r = 0; r < 4; r++)
#pragma unroll
                for (int cp = 0; cp < 4; cp++) ag[r][cp] = 0ULL;
            dot1<4>(ag, rhu, hb, bl, wg0p, 128);
            mstore(sw, q, sub, bl, 0, ag);
        }
        __syncthreads();
        p2_final(sw, lane, q, cta, 0, z_reg, xg_reg);
        bv++; gbar(bv * NCTA);

        // ---- P(1,1): x = new h0 ----
        {
            unsigned long long az[4][4], ar[4][4];
#pragma unroll
            for (int r = 0; r < 4; r++)
#pragma unroll
                for (int cp = 0; cp < 4; cp++) { az[r][cp] = 0ULL; ar[r][cp] = 0ULL; }
            dot2<4>(az, ar, h1u, hb, bl, wz1p, wr1p, 128);
            dot2<4>(az, ar, h0u, hb, bl, x1zp, x1rp, 128);
            mstore(sw, q, sub, bl, 0, az);
            mstore(sw, q, sub, bl, 4, ar);
        }
        {
            unsigned long long ag[4][4];
#pragma unroll
            for (int r = 0; r < 4; r++)
#pragma unroll
                for (int cp = 0; cp < 4; cp++) ag[r][cp] = 0ULL;
            dot1<4>(ag, h0u, hb, bl, x1gp, 128);
            mstore(sw, q, sub, bl, 8, ag);
        }
        __syncthreads();
        p1_final(sw, lane, q, cta, 1, (const float*)(g_h + HQ * Bx), z_reg, xg_reg);
        bv++; gbar(bv * NCTA);

        // ---- P(1,2) ----
        {
            unsigned long long ag[4][4];
#pragma unroll
            for (int r = 0; r < 4; r++)
#pragma unroll
                for (int cp = 0; cp < 4; cp++) ag[r][cp] = 0ULL;
            dot1<4>(ag, rhu, hb, bl, wg1p, 128);
            mstore(sw, q, sub, bl, 0, ag);
        }
        __syncthreads();
        p2_final(sw, lane, q, cta, 1, z_reg, xg_reg);
        bv++; gbar(bv * NCTA);

        // ---- P(2,1): x = new h1 ----
        {
            unsigned long long az[4][4], ar[4][4];
#pragma unroll
            for (int r = 0; r < 4; r++)
#pragma unroll
                for (int cp = 0; cp < 4; cp++) { az[r][cp] = 0ULL; ar[r][cp] = 0ULL; }
            dot2<4>(az, ar, h2u, hb, bl, wz2p, wr2p, 128);
            dot2<4>(az, ar, h1u, hb, bl, x2zp, x2rp, 128);
            mstore(sw, q, sub, bl, 0, az);
            mstore(sw, q, sub, bl, 4, ar);
        }
        {
            unsigned long long ag[4][4];
#pragma unroll
            for (int r = 0; r < 4; r++)
#pragma unroll
                for (int cp = 0; cp < 4; cp++) ag[r][cp] = 0ULL;
            dot1<4>(ag, h1u, hb, bl, x2gp, 128);
            mstore(sw, q, sub, bl, 8, ag);
        }
        __syncthreads();
        p1_final(sw, lane, q, cta, 2, (const float*)(g_h + 2 * HQ * Bx), z_reg, xg_reg);
        bv++; gbar(bv * NCTA);

        // ---- P(2,2) ----
        {
            unsigned long long ag[4][4];
#pragma unroll
            for (int r = 0; r < 4; r++)
#pragma unroll
                for (int cp = 0; cp < 4; cp++) ag[r][cp] = 0ULL;
            dot1<4>(ag, rhu, hb, bl, wg2p, 128);
            mstore(sw, q, sub, bl, 0, ag);
        }
        __syncthreads();
        p2_final(sw, lane, q, cta, 2, z_reg, xg_reg);
        bv++; gbar(bv * NCTA);
    }

    // y for the final timestep
    y_partial(sw, bl, sub, q);
    __syncthreads();
    if (q == 4) y_final(sw, lane, cta, out, Sx - 1);

    // hidden_out (B, L, H)
    if (q < 4) {
        const int c = q;
#pragma unroll
        for (int r = 0; r < 2; r++) {
            const int b = lane + 32 * r;
#pragma unroll
            for (int l = 0; l < Lx; l++) {
                float hv = ((const float*)g_h)[(((size_t)l * HQ + cta) * Bx + b) * 4 + c];
                out[(size_t)Bx * Sx * Ox + ((size_t)b * Lx + l) * Hx + nb + c] = hv;
            }
        }
    }
}

// ---------------------------------------------------------------------------
extern "C" void kernel_launch(void* const* d_in, const int* in_sizes, int n_in,
                              void* d_out, int out_size)
{
    const float* input = (const float*)d_in[0];
    const float* hs    = (const float*)d_in[1];
    const float* Wx0z  = (const float*)d_in[2];
    const float* Wx0r  = (const float*)d_in[3];
    const float* Wx0g  = (const float*)d_in[4];
    const float* Wxz   = (const float*)d_in[5];
    const float* Wxr   = (const float*)d_in[6];
    const float* Wxg   = (const float*)d_in[7];
    const float* Whz   = (const float*)d_in[8];
    const float* Whr   = (const float*)d_in[9];
    const float* Whg   = (const float*)d_in[10];
    const float* bz    = (const float*)d_in[11];
    const float* br    = (const float*)d_in[12];
    const float* bg    = (const float*)d_in[13];
    const float* Wy    = (const float*)d_in[14];
    const float* by    = (const float*)d_in[15];
    float* out = (float*)d_out;

    cudaFuncSetAttribute(gru_main, cudaFuncAttributeMaxDynamicSharedMemorySize, SMEM_BYTES);

    init_kernel<<<1024, 256>>>(input, hs);
    gru_main<<<NCTA, NTHR, SMEM_BYTES>>>(Wx0z, Wx0r, Wx0g, Wxz, Wxr, Wxg,
                                         Whz, Whr, Whg, bz, br, bg, Wy, by, out);
}